// round 12
// baseline (speedup 1.0000x reference)
#include <cuda_runtime.h>
#include <cuda_bf16.h>

// DynMorphConv2d: out[b,c,h,w] = max_{ki,kj} ( xpad[b,c,h+ki,w+kj]
//                                + sigmoid(x*gw[c]+gb[c]) * k[c,ki*3+kj] )
// B=8, C=192, H=W=128, zero pad.
//
// R11: R9 config (best: ring-4 rows, stride-2 packed pairs, FFMA2 taps,
// scalar FMNMX running max, tanh.approx gate, 6 CTAs/SM, MLP2, default
// cache policy) with unroll 8 to amortize loop overhead. Streaming cache
// hints reverted (R10 showed they cost L2 hit-rate on halo re-reads).

#define CH    192
#define HH    128
#define WW    128
#define RPW   32
#define NTHR  128

typedef unsigned long long u64;

__device__ __forceinline__ u64 pack2(float lo, float hi) {
    u64 r; asm("mov.b64 %0,{%1,%2};" : "=l"(r) : "f"(lo), "f"(hi)); return r;
}
__device__ __forceinline__ void unpack2(u64 v, float& lo, float& hi) {
    asm("mov.b64 {%0,%1},%2;" : "=f"(lo), "=f"(hi) : "l"(v));
}
__device__ __forceinline__ u64 ffma2(u64 a, u64 b, u64 c) {
    u64 d; asm("fma.rn.f32x2 %0,%1,%2,%3;" : "=l"(d) : "l"(a), "l"(b), "l"(c));
    return d;
}
__device__ __forceinline__ float tanha(float x) {
    float y; asm("tanh.approx.f32 %0,%1;" : "=f"(y) : "f"(x)); return y;
}

// stride-2 pairs: pl1=(l,x1) p02=(x0,x2) p13=(x1,x3) p2r=(x2,r)
struct Row { u64 pl1, p02, p13, p2r; };

__device__ __forceinline__ float4 ldrow(const float* __restrict__ xp,
                                        int gr, int lane)
{
    if ((unsigned)gr < (unsigned)HH)
        return __ldg(reinterpret_cast<const float4*>(xp + (size_t)gr * WW) + lane);
    return make_float4(0.f, 0.f, 0.f, 0.f);
}

__device__ __forceinline__ Row expand(float4 v, int lane)
{
    float l = __shfl_up_sync(0xffffffffu, v.w, 1);    // col-1
    float r = __shfl_down_sync(0xffffffffu, v.x, 1);  // col+4
    if (lane == 0)  l = 0.f;
    if (lane == 31) r = 0.f;
    Row R;
    R.pl1 = pack2(l,   v.y);
    R.p02 = pack2(v.x, v.z);
    R.p13 = pack2(v.y, v.w);
    R.p2r = pack2(v.z, r);
    return R;
}

// d = th*k + row (packed), fold halves into the two scalar running maxes
__device__ __forceinline__ void tapmax(u64 th, u64 k, u64 row,
                                       float& ma, float& mb)
{
    float lo, hi;
    unpack2(ffma2(th, k, row), lo, hi);   // unpack = reg-pair alias (free)
    ma = fmaxf(ma, lo);
    mb = fmaxf(mb, hi);
}

__global__ __launch_bounds__(NTHR, 6)
void dynmorph_kernel(const float* __restrict__ x,
                     const float* __restrict__ kern,
                     const float* __restrict__ gw,
                     const float* __restrict__ gb,
                     float* __restrict__ out)
{
    const int plane = blockIdx.x;            // b*C + c
    const int c     = plane % CH;
    const int warp  = threadIdx.x >> 5;
    const int lane  = threadIdx.x & 31;
    const int rs    = warp * RPW;

    const float* xp = x   + (size_t)plane * (HH * WW);
    float*       op = out + (size_t)plane * (HH * WW);

    u64 k2[9];
#pragma unroll
    for (int i = 0; i < 9; i++) {
        const float kv = __ldg(kern + c * 9 + i);
        k2[i] = pack2(kv, kv);
    }
    const float gwh = 0.5f * __ldg(gw + c);   // tanh half-angle fold
    const float gbh = 0.5f * __ldg(gb + c);

    // 4-slot ring: row (rs + j) lives in slot (j+1)&3
    Row W[4];
    W[0] = expand(ldrow(xp, rs - 1, lane), lane);
    W[1] = expand(ldrow(xp, rs,     lane), lane);
    W[2] = expand(ldrow(xp, rs + 1, lane), lane);
    // raw prefetch, 2 rows deep
    float4 vP0 = ldrow(xp, rs + 2, lane);
    float4 vP1 = ldrow(xp, rs + 3, lane);

#pragma unroll 8
    for (int r = 0; r < RPW; r++) {
        float4 vP2 = ldrow(xp, rs + r + 4, lane);   // 2 iterations ahead

        // expand row r+2 into slot (r+3)&3 (not used by this output)
        W[(r + 3) & 3] = expand(vP0, lane);

        const Row& A = W[ r      & 3];   // row r-1
        const Row& B = W[(r + 1) & 3];   // row r   (gate source)
        const Row& C = W[(r + 2) & 3];   // row r+1

        // gate: th_e = 0.5 + 0.5*tanh(x_e*gw/2 + gb/2)
        float x0, x1, x2, x3;
        unpack2(B.p02, x0, x2);
        unpack2(B.p13, x1, x3);
        const float th0 = fmaf(tanha(fmaf(x0, gwh, gbh)), 0.5f, 0.5f);
        const float th1 = fmaf(tanha(fmaf(x1, gwh, gbh)), 0.5f, 0.5f);
        const float th2 = fmaf(tanha(fmaf(x2, gwh, gbh)), 0.5f, 0.5f);
        const float th3 = fmaf(tanha(fmaf(x3, gwh, gbh)), 0.5f, 0.5f);
        const u64 th02 = pack2(th0, th2);
        const u64 th13 = pack2(th1, th3);

        // elements (0,2): taps at offsets -1,0,+1 are pl1, p02, p13
        float m0, m1, m2, m3;
        {
            float lo, hi;
            unpack2(ffma2(th02, k2[0], A.pl1), lo, hi);
            m0 = lo; m2 = hi;
        }
        tapmax(th02, k2[1], A.p02, m0, m2);
        tapmax(th02, k2[2], A.p13, m0, m2);
        tapmax(th02, k2[3], B.pl1, m0, m2);
        tapmax(th02, k2[4], B.p02, m0, m2);
        tapmax(th02, k2[5], B.p13, m0, m2);
        tapmax(th02, k2[6], C.pl1, m0, m2);
        tapmax(th02, k2[7], C.p02, m0, m2);
        tapmax(th02, k2[8], C.p13, m0, m2);

        // elements (1,3): taps are p02, p13, p2r
        {
            float lo, hi;
            unpack2(ffma2(th13, k2[0], A.p02), lo, hi);
            m1 = lo; m3 = hi;
        }
        tapmax(th13, k2[1], A.p13, m1, m3);
        tapmax(th13, k2[2], A.p2r, m1, m3);
        tapmax(th13, k2[3], B.p02, m1, m3);
        tapmax(th13, k2[4], B.p13, m1, m3);
        tapmax(th13, k2[5], B.p2r, m1, m3);
        tapmax(th13, k2[6], C.p02, m1, m3);
        tapmax(th13, k2[7], C.p13, m1, m3);
        tapmax(th13, k2[8], C.p2r, m1, m3);

        reinterpret_cast<float4*>(op + (size_t)(rs + r) * WW)[lane] =
            make_float4(m0, m1, m2, m3);

        vP0 = vP1; vP1 = vP2;   // period-2 shift under unroll 8 -> renamed, free
    }
}

extern "C" void kernel_launch(void* const* d_in, const int* in_sizes, int n_in,
                              void* d_out, int out_size)
{
    const float* x    = (const float*)d_in[0];   // [8,192,128,128]
    const float* kern = (const float*)d_in[1];   // [192,9]
    const float* gwp  = (const float*)d_in[2];   // [192]
    const float* gbp  = (const float*)d_in[3];   // [192]
    float*       out  = (float*)d_out;

    const int B = in_sizes[0] / (CH * HH * WW);  // 8
    const int grid = B * CH;                     // 1536 plane blocks

    dynmorph_kernel<<<grid, NTHR>>>(x, kern, gwp, gbp, out);
}

// round 14
// speedup vs baseline: 1.0557x; 1.0557x over previous
#include <cuda_runtime.h>
#include <cuda_bf16.h>

// DynMorphConv2d: out[b,c,h,w] = max_{ki,kj} ( xpad[b,c,h+ki,w+kj]
//                                + sigmoid(x*gw[c]+gb[c]) * k[c,ki*3+kj] )
// B=8, C=192, H=W=128, zero pad.
//
// FINAL (== R9, the empirically converged optimum):
//  - register-rolling rows, no smem/barriers; warp = 32-row strip
//  - 4-slot row ring matched to unroll 4 -> zero rotation MOVs
//  - stride-2 packed pairs (4 x u64 per row), FFMA2 taps
//  - scalar FMNMX running max (unpack of f32x2 = free reg-pair alias)
//  - sigmoid via tanh.approx half-angle fold
//  - 128 thr, 6 CTAs/SM, 2-deep row prefetch (MLP2), default cache policy
// Kernel ~30.8us, ~6.5 TB/s true DRAM traffic (~82% of 8 TB/s spec).

#define CH    192
#define HH    128
#define WW    128
#define RPW   32
#define NTHR  128

typedef unsigned long long u64;

__device__ __forceinline__ u64 pack2(float lo, float hi) {
    u64 r; asm("mov.b64 %0,{%1,%2};" : "=l"(r) : "f"(lo), "f"(hi)); return r;
}
__device__ __forceinline__ void unpack2(u64 v, float& lo, float& hi) {
    asm("mov.b64 {%0,%1},%2;" : "=f"(lo), "=f"(hi) : "l"(v));
}
__device__ __forceinline__ u64 ffma2(u64 a, u64 b, u64 c) {
    u64 d; asm("fma.rn.f32x2 %0,%1,%2,%3;" : "=l"(d) : "l"(a), "l"(b), "l"(c));
    return d;
}
__device__ __forceinline__ float tanha(float x) {
    float y; asm("tanh.approx.f32 %0,%1;" : "=f"(y) : "f"(x)); return y;
}

// stride-2 pairs: pl1=(l,x1) p02=(x0,x2) p13=(x1,x3) p2r=(x2,r)
struct Row { u64 pl1, p02, p13, p2r; };

__device__ __forceinline__ float4 ldrow(const float* __restrict__ xp,
                                        int gr, int lane)
{
    if ((unsigned)gr < (unsigned)HH)
        return __ldg(reinterpret_cast<const float4*>(xp + (size_t)gr * WW) + lane);
    return make_float4(0.f, 0.f, 0.f, 0.f);
}

__device__ __forceinline__ Row expand(float4 v, int lane)
{
    float l = __shfl_up_sync(0xffffffffu, v.w, 1);    // col-1
    float r = __shfl_down_sync(0xffffffffu, v.x, 1);  // col+4
    if (lane == 0)  l = 0.f;
    if (lane == 31) r = 0.f;
    Row R;
    R.pl1 = pack2(l,   v.y);
    R.p02 = pack2(v.x, v.z);
    R.p13 = pack2(v.y, v.w);
    R.p2r = pack2(v.z, r);
    return R;
}

// d = th*k + row (packed), fold halves into the two scalar running maxes
__device__ __forceinline__ void tapmax(u64 th, u64 k, u64 row,
                                       float& ma, float& mb)
{
    float lo, hi;
    unpack2(ffma2(th, k, row), lo, hi);   // unpack = reg-pair alias (free)
    ma = fmaxf(ma, lo);
    mb = fmaxf(mb, hi);
}

__global__ __launch_bounds__(NTHR, 6)
void dynmorph_kernel(const float* __restrict__ x,
                     const float* __restrict__ kern,
                     const float* __restrict__ gw,
                     const float* __restrict__ gb,
                     float* __restrict__ out)
{
    const int plane = blockIdx.x;            // b*C + c
    const int c     = plane % CH;
    const int warp  = threadIdx.x >> 5;
    const int lane  = threadIdx.x & 31;
    const int rs    = warp * RPW;

    const float* xp = x   + (size_t)plane * (HH * WW);
    float*       op = out + (size_t)plane * (HH * WW);

    u64 k2[9];
#pragma unroll
    for (int i = 0; i < 9; i++) {
        const float kv = __ldg(kern + c * 9 + i);
        k2[i] = pack2(kv, kv);
    }
    const float gwh = 0.5f * __ldg(gw + c);   // tanh half-angle fold
    const float gbh = 0.5f * __ldg(gb + c);

    // 4-slot ring: row (rs + j) lives in slot (j+1)&3
    Row W[4];
    W[0] = expand(ldrow(xp, rs - 1, lane), lane);
    W[1] = expand(ldrow(xp, rs,     lane), lane);
    W[2] = expand(ldrow(xp, rs + 1, lane), lane);
    // raw prefetch, 2 rows deep
    float4 vP0 = ldrow(xp, rs + 2, lane);
    float4 vP1 = ldrow(xp, rs + 3, lane);

#pragma unroll 4
    for (int r = 0; r < RPW; r++) {
        float4 vP2 = ldrow(xp, rs + r + 4, lane);   // 2 iterations ahead

        // expand row r+2 into slot (r+3)&3 (not used by this output)
        W[(r + 3) & 3] = expand(vP0, lane);

        const Row& A = W[ r      & 3];   // row r-1
        const Row& B = W[(r + 1) & 3];   // row r   (gate source)
        const Row& C = W[(r + 2) & 3];   // row r+1

        // gate: th_e = 0.5 + 0.5*tanh(x_e*gw/2 + gb/2)
        float x0, x1, x2, x3;
        unpack2(B.p02, x0, x2);
        unpack2(B.p13, x1, x3);
        const float th0 = fmaf(tanha(fmaf(x0, gwh, gbh)), 0.5f, 0.5f);
        const float th1 = fmaf(tanha(fmaf(x1, gwh, gbh)), 0.5f, 0.5f);
        const float th2 = fmaf(tanha(fmaf(x2, gwh, gbh)), 0.5f, 0.5f);
        const float th3 = fmaf(tanha(fmaf(x3, gwh, gbh)), 0.5f, 0.5f);
        const u64 th02 = pack2(th0, th2);
        const u64 th13 = pack2(th1, th3);

        // elements (0,2): taps at offsets -1,0,+1 are pl1, p02, p13
        float m0, m1, m2, m3;
        {
            float lo, hi;
            unpack2(ffma2(th02, k2[0], A.pl1), lo, hi);
            m0 = lo; m2 = hi;
        }
        tapmax(th02, k2[1], A.p02, m0, m2);
        tapmax(th02, k2[2], A.p13, m0, m2);
        tapmax(th02, k2[3], B.pl1, m0, m2);
        tapmax(th02, k2[4], B.p02, m0, m2);
        tapmax(th02, k2[5], B.p13, m0, m2);
        tapmax(th02, k2[6], C.pl1, m0, m2);
        tapmax(th02, k2[7], C.p02, m0, m2);
        tapmax(th02, k2[8], C.p13, m0, m2);

        // elements (1,3): taps are p02, p13, p2r
        {
            float lo, hi;
            unpack2(ffma2(th13, k2[0], A.p02), lo, hi);
            m1 = lo; m3 = hi;
        }
        tapmax(th13, k2[1], A.p13, m1, m3);
        tapmax(th13, k2[2], A.p2r, m1, m3);
        tapmax(th13, k2[3], B.p02, m1, m3);
        tapmax(th13, k2[4], B.p13, m1, m3);
        tapmax(th13, k2[5], B.p2r, m1, m3);
        tapmax(th13, k2[6], C.p02, m1, m3);
        tapmax(th13, k2[7], C.p13, m1, m3);
        tapmax(th13, k2[8], C.p2r, m1, m3);

        reinterpret_cast<float4*>(op + (size_t)(rs + r) * WW)[lane] =
            make_float4(m0, m1, m2, m3);

        vP0 = vP1; vP1 = vP2;   // period-2 shift under unroll 4 -> renamed, free
    }
}

extern "C" void kernel_launch(void* const* d_in, const int* in_sizes, int n_in,
                              void* d_out, int out_size)
{
    const float* x    = (const float*)d_in[0];   // [8,192,128,128]
    const float* kern = (const float*)d_in[1];   // [192,9]
    const float* gwp  = (const float*)d_in[2];   // [192]
    const float* gbp  = (const float*)d_in[3];   // [192]
    float*       out  = (float*)d_out;

    const int B = in_sizes[0] / (CH * HH * WW);  // 8
    const int grid = B * CH;                     // 1536 plane blocks

    dynmorph_kernel<<<grid, NTHR>>>(x, kern, gwp, gbp, out);
}